// round 2
// baseline (speedup 1.0000x reference)
#include <cuda_runtime.h>
#include <stdint.h>

#define N_NODES 100000
#define N_EDGES 800000
#define HIDDEN  128

// ---------------- scratch (static device memory; no allocation) -------------
__device__ float g_S1[(size_t)N_NODES * HIDDEN];   // sum over edges (i,j) of h[j], indexed by i
__device__ float g_S2[(size_t)N_NODES * HIDDEN];   // sum over edges (i,j) of h[i], indexed by j
__device__ int   g_d1[N_NODES];                    // out-degree (src)
__device__ int   g_d2[N_NODES];                    // in-degree  (dst)
__device__ int   g_off1[N_NODES];
__device__ int   g_off2[N_NODES];
__device__ int   g_cur1[N_NODES];
__device__ int   g_cur2[N_NODES];
__device__ int   g_csr1[N_EDGES];                  // neighbors (dst) grouped by src
__device__ int   g_csr2[N_EDGES];                  // neighbors (src) grouped by dst

// ---------------- helpers ---------------------------------------------------
__device__ __forceinline__ unsigned long long pack2(float lo, float hi) {
    unsigned long long r;
    asm("mov.b64 %0, {%1, %2};" : "=l"(r) : "f"(lo), "f"(hi));
    return r;
}
__device__ __forceinline__ float2 unpack2(unsigned long long v) {
    float2 f;
    asm("mov.b64 {%0, %1}, %2;" : "=f"(f.x), "=f"(f.y) : "l"(v));
    return f;
}
__device__ __forceinline__ void fma2(unsigned long long& acc,
                                     unsigned long long a,
                                     unsigned long long b) {
    asm("fma.rn.f32x2 %0, %1, %2, %0;" : "+l"(acc) : "l"(a), "l"(b));
}

// ---------------- kernel 1: zero degree counters -----------------------------
__global__ void zero_deg_kernel() {
    int i = blockIdx.x * blockDim.x + threadIdx.x;
    if (i < N_NODES) { g_d1[i] = 0; g_d2[i] = 0; }
}

// ---------------- kernel 2: degree histogram ---------------------------------
__global__ void hist_kernel(const int* __restrict__ esrc,
                            const int* __restrict__ edst) {
    int e = blockIdx.x * blockDim.x + threadIdx.x;
    if (e < N_EDGES) {
        atomicAdd(&g_d1[esrc[e]], 1);
        atomicAdd(&g_d2[edst[e]], 1);
    }
}

// ---------------- kernel 3: exclusive scan (single block, both arrays) -------
__global__ void __launch_bounds__(1024) scan_kernel() {
    __shared__ int sh[1024];
    const int t  = threadIdx.x;
    const int CH = (N_NODES + 1023) / 1024;      // 98
    const int s0 = t * CH;
    const int s1 = (s0 + CH < N_NODES) ? s0 + CH : N_NODES;

#pragma unroll 1
    for (int which = 0; which < 2; ++which) {
        const int* deg = which ? g_d2 : g_d1;
        int* off = which ? g_off2 : g_off1;
        int* cur = which ? g_cur2 : g_cur1;

        int sum = 0;
        for (int i = s0; i < s1; ++i) sum += deg[i];
        sh[t] = sum;
        __syncthreads();
        // Kogge-Stone inclusive scan
        for (int o = 1; o < 1024; o <<= 1) {
            int tmp = (t >= o) ? sh[t - o] : 0;
            __syncthreads();
            sh[t] += tmp;
            __syncthreads();
        }
        int run = sh[t] - sum;                    // exclusive prefix
        __syncthreads();
        for (int i = s0; i < s1; ++i) {
            int d = deg[i];
            off[i] = run;
            cur[i] = run;
            run += d;
        }
        __syncthreads();
    }
}

// ---------------- kernel 4: fill CSR adjacency -------------------------------
__global__ void fill_kernel(const int* __restrict__ esrc,
                            const int* __restrict__ edst) {
    int e = blockIdx.x * blockDim.x + threadIdx.x;
    if (e < N_EDGES) {
        int s = esrc[e], d = edst[e];
        int p = atomicAdd(&g_cur1[s], 1);
        g_csr1[p] = d;
        int q = atomicAdd(&g_cur2[d], 1);
        g_csr2[q] = s;
    }
}

// ---------------- kernel 5: per-node gather aggregation ----------------------
// warp w < N_NODES:  S1[w] = sum_{j in csr1[w]} h[j]
// warp w >= N_NODES: S2[n] = sum_{j in csr2[n]} h[j]
__global__ void __launch_bounds__(256) agg_kernel(const float* __restrict__ h) {
    int w    = (blockIdx.x * blockDim.x + threadIdx.x) >> 5;
    int lane = threadIdx.x & 31;
    if (w >= 2 * N_NODES) return;

    const bool second = (w >= N_NODES);
    const int  n      = second ? w - N_NODES : w;
    const int* off = second ? g_off2 : g_off1;
    const int* deg = second ? g_d2   : g_d1;
    const int* csr = second ? g_csr2 : g_csr1;
    float*     S   = second ? g_S2   : g_S1;

    const int a   = off[n];
    const int cnt = deg[n];

    float4 acc = make_float4(0.f, 0.f, 0.f, 0.f);
    int k = 0;
    for (; k + 4 <= cnt; k += 4) {
        int j0 = csr[a + k + 0];
        int j1 = csr[a + k + 1];
        int j2 = csr[a + k + 2];
        int j3 = csr[a + k + 3];
        float4 v0 = ((const float4*)(h + (size_t)j0 * HIDDEN))[lane];
        float4 v1 = ((const float4*)(h + (size_t)j1 * HIDDEN))[lane];
        float4 v2 = ((const float4*)(h + (size_t)j2 * HIDDEN))[lane];
        float4 v3 = ((const float4*)(h + (size_t)j3 * HIDDEN))[lane];
        acc.x += (v0.x + v1.x) + (v2.x + v3.x);
        acc.y += (v0.y + v1.y) + (v2.y + v3.y);
        acc.z += (v0.z + v1.z) + (v2.z + v3.z);
        acc.w += (v0.w + v1.w) + (v2.w + v3.w);
    }
    for (; k < cnt; ++k) {
        int j = csr[a + k];
        float4 v = ((const float4*)(h + (size_t)j * HIDDEN))[lane];
        acc.x += v.x; acc.y += v.y; acc.z += v.z; acc.w += v.w;
    }
    ((float4*)(S + (size_t)n * HIDDEN))[lane] = acc;
}

// ---------------- kernel 6: fused GEMM + bias + relu ------------------------
// out[i] = relu( S1[i]@Ww^T + d1[i]*Wb + h[i]@Wsw^T + Wsb + S2[i]@Wtw^T + d2[i]*Wtb )
__global__ void __launch_bounds__(256) gemm_kernel(const float* __restrict__ h,
                                                   const float* __restrict__ Ww,
                                                   const float* __restrict__ Wb,
                                                   const float* __restrict__ Wsw,
                                                   const float* __restrict__ Wsb,
                                                   const float* __restrict__ Wtw,
                                                   const float* __restrict__ Wtb,
                                                   float* __restrict__ out) {
    __shared__ float As[32][68];    // [k][row]
    __shared__ float Ws[32][132];   // [k][col]

    const int tid = threadIdx.x;
    const int tx  = tid & 31;       // col group: cols tx*4 .. tx*4+3
    const int ty  = tid >> 5;       // row group: rows ty*8 .. ty*8+7
    const int row0 = blockIdx.x * 64;

    unsigned long long acc[4][4];
#pragma unroll
    for (int p = 0; p < 4; ++p)
#pragma unroll
        for (int c = 0; c < 4; ++c) acc[p][c] = 0ull;

#pragma unroll 1
    for (int chunk = 0; chunk < 12; ++chunk) {
        const int sidx = chunk >> 2;          // 0: S1/Ww, 1: h/Wsw, 2: S2/Wtw
        const int k0   = (chunk & 3) * 32;
        const float* A = (sidx == 0) ? g_S1 : (sidx == 1) ? h : g_S2;
        const float* W = (sidx == 0) ? Ww   : (sidx == 1) ? Wsw : Wtw;

        __syncthreads();
#pragma unroll
        for (int j = 0; j < 2; ++j) {
            int lin = tid + j * 256;
            int r   = lin >> 3;
            int g   = lin & 7;
            float4 v = make_float4(0.f, 0.f, 0.f, 0.f);
            int row = row0 + r;
            if (row < N_NODES)
                v = *(const float4*)(A + (size_t)row * HIDDEN + k0 + g * 4);
            int kk = g * 4;
            As[kk + 0][r] = v.x;
            As[kk + 1][r] = v.y;
            As[kk + 2][r] = v.z;
            As[kk + 3][r] = v.w;
        }
#pragma unroll
        for (int j = 0; j < 4; ++j) {
            int lin = tid + j * 256;
            int c   = lin >> 3;
            int g   = lin & 7;
            float4 v = *(const float4*)(W + (size_t)c * HIDDEN + k0 + g * 4);
            int kk = g * 4;
            Ws[kk + 0][c] = v.x;
            Ws[kk + 1][c] = v.y;
            Ws[kk + 2][c] = v.z;
            Ws[kk + 3][c] = v.w;
        }
        __syncthreads();

#pragma unroll
        for (int kk = 0; kk < 32; ++kk) {
            ulonglong2 a01 = *(const ulonglong2*)&As[kk][ty * 8];
            ulonglong2 a23 = *(const ulonglong2*)&As[kk][ty * 8 + 4];
            float4 w = *(const float4*)&Ws[kk][tx * 4];
            unsigned long long w0 = pack2(w.x, w.x);
            unsigned long long w1 = pack2(w.y, w.y);
            unsigned long long w2 = pack2(w.z, w.z);
            unsigned long long w3 = pack2(w.w, w.w);

            fma2(acc[0][0], a01.x, w0); fma2(acc[0][1], a01.x, w1);
            fma2(acc[0][2], a01.x, w2); fma2(acc[0][3], a01.x, w3);
            fma2(acc[1][0], a01.y, w0); fma2(acc[1][1], a01.y, w1);
            fma2(acc[1][2], a01.y, w2); fma2(acc[1][3], a01.y, w3);
            fma2(acc[2][0], a23.x, w0); fma2(acc[2][1], a23.x, w1);
            fma2(acc[2][2], a23.x, w2); fma2(acc[2][3], a23.x, w3);
            fma2(acc[3][0], a23.y, w0); fma2(acc[3][1], a23.y, w1);
            fma2(acc[3][2], a23.y, w2); fma2(acc[3][3], a23.y, w3);
        }
    }

    const int colbase = tx * 4;
    float4 bw  = *(const float4*)(Wb  + colbase);
    float4 bs  = *(const float4*)(Wsb + colbase);
    float4 bt  = *(const float4*)(Wtb + colbase);

#pragma unroll
    for (int p = 0; p < 4; ++p) {
        int re = row0 + ty * 8 + 2 * p;
        if (re >= N_NODES) break;
        float2 v0 = unpack2(acc[p][0]);
        float2 v1 = unpack2(acc[p][1]);
        float2 v2 = unpack2(acc[p][2]);
        float2 v3 = unpack2(acc[p][3]);

        {
            float f1 = (float)g_d1[re];
            float f2 = (float)g_d2[re];
            float4 o;
            o.x = v0.x + f1 * bw.x + bs.x + f2 * bt.x;
            o.y = v1.x + f1 * bw.y + bs.y + f2 * bt.y;
            o.z = v2.x + f1 * bw.z + bs.z + f2 * bt.z;
            o.w = v3.x + f1 * bw.w + bs.w + f2 * bt.w;
            o.x = fmaxf(o.x, 0.f); o.y = fmaxf(o.y, 0.f);
            o.z = fmaxf(o.z, 0.f); o.w = fmaxf(o.w, 0.f);
            *(float4*)(out + (size_t)re * HIDDEN + colbase) = o;
        }
        int ro = re + 1;
        if (ro < N_NODES) {
            float f1 = (float)g_d1[ro];
            float f2 = (float)g_d2[ro];
            float4 o;
            o.x = v0.y + f1 * bw.x + bs.x + f2 * bt.x;
            o.y = v1.y + f1 * bw.y + bs.y + f2 * bt.y;
            o.z = v2.y + f1 * bw.z + bs.z + f2 * bt.z;
            o.w = v3.y + f1 * bw.w + bs.w + f2 * bt.w;
            o.x = fmaxf(o.x, 0.f); o.y = fmaxf(o.y, 0.f);
            o.z = fmaxf(o.z, 0.f); o.w = fmaxf(o.w, 0.f);
            *(float4*)(out + (size_t)ro * HIDDEN + colbase) = o;
        }
    }
}

// ---------------- launch -----------------------------------------------------
extern "C" void kernel_launch(void* const* d_in, const int* in_sizes, int n_in,
                              void* d_out, int out_size) {
    const float* h    = (const float*)d_in[0];
    const int*   esrc = (const int*)  d_in[1];
    const int*   edst = (const int*)  d_in[2];
    const float* Ww   = (const float*)d_in[3];
    const float* Wb   = (const float*)d_in[4];
    const float* Wsw  = (const float*)d_in[5];
    const float* Wsb  = (const float*)d_in[6];
    const float* Wtw  = (const float*)d_in[7];
    const float* Wtb  = (const float*)d_in[8];
    float* out = (float*)d_out;

    zero_deg_kernel<<<(N_NODES + 255) / 256, 256>>>();
    hist_kernel<<<(N_EDGES + 255) / 256, 256>>>(esrc, edst);
    scan_kernel<<<1, 1024>>>();
    fill_kernel<<<(N_EDGES + 255) / 256, 256>>>(esrc, edst);
    agg_kernel<<<(2 * N_NODES + 7) / 8, 256>>>(h);
    gemm_kernel<<<(N_NODES + 63) / 64, 256>>>(h, Ww, Wb, Wsw, Wsb, Wtw, Wtb, out);
}

// round 3
// speedup vs baseline: 1.4339x; 1.4339x over previous
#include <cuda_runtime.h>
#include <stdint.h>

#define N_NODES 100000
#define N_EDGES 800000
#define HIDDEN  128

// ---------------- scratch (static device memory; no allocation) -------------
__device__ float g_S1[(size_t)N_NODES * HIDDEN];   // sum over edges (i,j) of h[j], indexed by i
__device__ float g_S2[(size_t)N_NODES * HIDDEN];   // sum over edges (i,j) of h[i], indexed by j
__device__ int   g_d1[N_NODES];                    // out-degree (src)
__device__ int   g_d2[N_NODES];                    // in-degree  (dst)

// ---------------- helpers ---------------------------------------------------
__device__ __forceinline__ unsigned long long pack2(float lo, float hi) {
    unsigned long long r;
    asm("mov.b64 %0, {%1, %2};" : "=l"(r) : "f"(lo), "f"(hi));
    return r;
}
__device__ __forceinline__ float2 unpack2(unsigned long long v) {
    float2 f;
    asm("mov.b64 {%0, %1}, %2;" : "=f"(f.x), "=f"(f.y) : "l"(v));
    return f;
}
__device__ __forceinline__ void fma2(unsigned long long& acc,
                                     unsigned long long a,
                                     unsigned long long b) {
    asm("fma.rn.f32x2 %0, %1, %2, %0;" : "+l"(acc) : "l"(a), "l"(b));
}

// ---------------- kernel 1: zero scratch ------------------------------------
__global__ void zero_kernel() {
    size_t tid    = (size_t)blockIdx.x * blockDim.x + threadIdx.x;
    size_t stride = (size_t)gridDim.x * blockDim.x;
    const size_t n4 = (size_t)N_NODES * HIDDEN / 4;
    float4 z = make_float4(0.f, 0.f, 0.f, 0.f);
    for (size_t j = tid; j < n4; j += stride) {
        ((float4*)g_S1)[j] = z;
        ((float4*)g_S2)[j] = z;
    }
    for (size_t j = tid; j < N_NODES; j += stride) {
        g_d1[j] = 0;
        g_d2[j] = 0;
    }
}

// ---------------- kernel 2a: edge pass 1 (S1 only; working set h+S1 in L2) --
// S1[s] += h[d] for each edge (s,d)
__global__ void __launch_bounds__(256) edge1_kernel(const float* __restrict__ h,
                                                    const int*   __restrict__ esrc,
                                                    const int*   __restrict__ edst) {
    int warp = (blockIdx.x * blockDim.x + threadIdx.x) >> 5;
    int lane = threadIdx.x & 31;
    if (warp >= N_EDGES) return;
    int s = esrc[warp];
    int d = edst[warp];
    float4 v = ((const float4*)(h + (size_t)d * HIDDEN))[lane];
    atomicAdd(((float4*)(g_S1 + (size_t)s * HIDDEN)) + lane, v);
    if (lane == 0) atomicAdd(&g_d1[s], 1);
}

// ---------------- kernel 2b: edge pass 2 (S2 only; working set h+S2 in L2) --
// S2[d] += h[s] for each edge (s,d)
__global__ void __launch_bounds__(256) edge2_kernel(const float* __restrict__ h,
                                                    const int*   __restrict__ esrc,
                                                    const int*   __restrict__ edst) {
    int warp = (blockIdx.x * blockDim.x + threadIdx.x) >> 5;
    int lane = threadIdx.x & 31;
    if (warp >= N_EDGES) return;
    int s = esrc[warp];
    int d = edst[warp];
    float4 v = ((const float4*)(h + (size_t)s * HIDDEN))[lane];
    atomicAdd(((float4*)(g_S2 + (size_t)d * HIDDEN)) + lane, v);
    if (lane == 0) atomicAdd(&g_d2[d], 1);
}

// ---------------- kernel 3: fused GEMM + bias + relu ------------------------
// out[i] = relu( S1[i]@Ww^T + d1[i]*Wb + h[i]@Wsw^T + Wsb + S2[i]@Wtw^T + d2[i]*Wtb )
// 64 rows x 128 cols per block; 256 threads; thread tile 8 rows x 4 cols.
// Register-prefetch double buffering over the 12 K-chunks (3 sources x 4 x 32k).
__global__ void __launch_bounds__(256) gemm_kernel(const float* __restrict__ h,
                                                   const float* __restrict__ Ww,
                                                   const float* __restrict__ Wb,
                                                   const float* __restrict__ Wsw,
                                                   const float* __restrict__ Wsb,
                                                   const float* __restrict__ Wtw,
                                                   const float* __restrict__ Wtb,
                                                   float* __restrict__ out) {
    __shared__ float As[32][68];    // [k][row]
    __shared__ float Ws[32][132];   // [k][col]

    const int tid = threadIdx.x;
    const int tx  = tid & 31;       // col group: cols tx*4 .. tx*4+3
    const int ty  = tid >> 5;       // row group: rows ty*8 .. ty*8+7
    const int row0 = blockIdx.x * 64;

    const float* Alist[3];
    Alist[0] = g_S1; Alist[1] = h; Alist[2] = g_S2;
    const float* Wlist[3];
    Wlist[0] = Ww; Wlist[1] = Wsw; Wlist[2] = Wtw;

    // per-thread fixed load coordinates
    int ar[2], ag[2], arow_ok[2];
#pragma unroll
    for (int j = 0; j < 2; ++j) {
        int lin = tid + j * 256;
        ar[j] = lin >> 3;                 // 0..63
        ag[j] = lin & 7;                  // float4 group
        arow_ok[j] = (row0 + ar[j]) < N_NODES;
    }
    int wc[4], wg[4];
#pragma unroll
    for (int j = 0; j < 4; ++j) {
        int lin = tid + j * 256;
        wc[j] = lin >> 3;                 // 0..127
        wg[j] = lin & 7;
    }

    unsigned long long acc[4][4];
#pragma unroll
    for (int p = 0; p < 4; ++p)
#pragma unroll
        for (int c = 0; c < 4; ++c) acc[p][c] = 0ull;

    float4 pa[2], pw[4];

    // prefetch chunk 0
    {
        const float* A = Alist[0];
        const float* W = Wlist[0];
#pragma unroll
        for (int j = 0; j < 2; ++j) {
            pa[j] = make_float4(0.f, 0.f, 0.f, 0.f);
            if (arow_ok[j])
                pa[j] = *(const float4*)(A + (size_t)(row0 + ar[j]) * HIDDEN + ag[j] * 4);
        }
#pragma unroll
        for (int j = 0; j < 4; ++j)
            pw[j] = *(const float4*)(W + (size_t)wc[j] * HIDDEN + wg[j] * 4);
    }

#pragma unroll 1
    for (int chunk = 0; chunk < 12; ++chunk) {
        // store prefetched tile to smem
        __syncthreads();
#pragma unroll
        for (int j = 0; j < 2; ++j) {
            int kk = ag[j] * 4;
            int r  = ar[j];
            As[kk + 0][r] = pa[j].x;
            As[kk + 1][r] = pa[j].y;
            As[kk + 2][r] = pa[j].z;
            As[kk + 3][r] = pa[j].w;
        }
#pragma unroll
        for (int j = 0; j < 4; ++j) {
            int kk = wg[j] * 4;
            int c  = wc[j];
            Ws[kk + 0][c] = pw[j].x;
            Ws[kk + 1][c] = pw[j].y;
            Ws[kk + 2][c] = pw[j].z;
            Ws[kk + 3][c] = pw[j].w;
        }
        __syncthreads();

        // prefetch next chunk while computing this one
        if (chunk < 11) {
            int nc   = chunk + 1;
            int sidx = nc >> 2;
            int k0   = (nc & 3) * 32;
            const float* A = Alist[sidx];
            const float* W = Wlist[sidx];
#pragma unroll
            for (int j = 0; j < 2; ++j) {
                pa[j] = make_float4(0.f, 0.f, 0.f, 0.f);
                if (arow_ok[j])
                    pa[j] = *(const float4*)(A + (size_t)(row0 + ar[j]) * HIDDEN + k0 + ag[j] * 4);
            }
#pragma unroll
            for (int j = 0; j < 4; ++j)
                pw[j] = *(const float4*)(W + (size_t)wc[j] * HIDDEN + k0 + wg[j] * 4);
        }

#pragma unroll
        for (int kk = 0; kk < 32; ++kk) {
            ulonglong2 a01 = *(const ulonglong2*)&As[kk][ty * 8];
            ulonglong2 a23 = *(const ulonglong2*)&As[kk][ty * 8 + 4];
            float4 w = *(const float4*)&Ws[kk][tx * 4];
            unsigned long long w0 = pack2(w.x, w.x);
            unsigned long long w1 = pack2(w.y, w.y);
            unsigned long long w2 = pack2(w.z, w.z);
            unsigned long long w3 = pack2(w.w, w.w);

            fma2(acc[0][0], a01.x, w0); fma2(acc[0][1], a01.x, w1);
            fma2(acc[0][2], a01.x, w2); fma2(acc[0][3], a01.x, w3);
            fma2(acc[1][0], a01.y, w0); fma2(acc[1][1], a01.y, w1);
            fma2(acc[1][2], a01.y, w2); fma2(acc[1][3], a01.y, w3);
            fma2(acc[2][0], a23.x, w0); fma2(acc[2][1], a23.x, w1);
            fma2(acc[2][2], a23.x, w2); fma2(acc[2][3], a23.x, w3);
            fma2(acc[3][0], a23.y, w0); fma2(acc[3][1], a23.y, w1);
            fma2(acc[3][2], a23.y, w2); fma2(acc[3][3], a23.y, w3);
        }
    }

    // epilogue: degree-scaled bias + relu
    const int colbase = tx * 4;
    float4 bw  = *(const float4*)(Wb  + colbase);
    float4 bs  = *(const float4*)(Wsb + colbase);
    float4 bt  = *(const float4*)(Wtb + colbase);

#pragma unroll
    for (int p = 0; p < 4; ++p) {
        int re = row0 + ty * 8 + 2 * p;
        if (re >= N_NODES) break;
        float2 v0 = unpack2(acc[p][0]);
        float2 v1 = unpack2(acc[p][1]);
        float2 v2 = unpack2(acc[p][2]);
        float2 v3 = unpack2(acc[p][3]);

        {
            float f1 = (float)g_d1[re];
            float f2 = (float)g_d2[re];
            float4 o;
            o.x = v0.x + f1 * bw.x + bs.x + f2 * bt.x;
            o.y = v1.x + f1 * bw.y + bs.y + f2 * bt.y;
            o.z = v2.x + f1 * bw.z + bs.z + f2 * bt.z;
            o.w = v3.x + f1 * bw.w + bs.w + f2 * bt.w;
            o.x = fmaxf(o.x, 0.f); o.y = fmaxf(o.y, 0.f);
            o.z = fmaxf(o.z, 0.f); o.w = fmaxf(o.w, 0.f);
            *(float4*)(out + (size_t)re * HIDDEN + colbase) = o;
        }
        int ro = re + 1;
        if (ro < N_NODES) {
            float f1 = (float)g_d1[ro];
            float f2 = (float)g_d2[ro];
            float4 o;
            o.x = v0.y + f1 * bw.x + bs.x + f2 * bt.x;
            o.y = v1.y + f1 * bw.y + bs.y + f2 * bt.y;
            o.z = v2.y + f1 * bw.z + bs.z + f2 * bt.z;
            o.w = v3.y + f1 * bw.w + bs.w + f2 * bt.w;
            o.x = fmaxf(o.x, 0.f); o.y = fmaxf(o.y, 0.f);
            o.z = fmaxf(o.z, 0.f); o.w = fmaxf(o.w, 0.f);
            *(float4*)(out + (size_t)ro * HIDDEN + colbase) = o;
        }
    }
}

// ---------------- launch -----------------------------------------------------
extern "C" void kernel_launch(void* const* d_in, const int* in_sizes, int n_in,
                              void* d_out, int out_size) {
    const float* h    = (const float*)d_in[0];
    const int*   esrc = (const int*)  d_in[1];
    const int*   edst = (const int*)  d_in[2];
    const float* Ww   = (const float*)d_in[3];
    const float* Wb   = (const float*)d_in[4];
    const float* Wsw  = (const float*)d_in[5];
    const float* Wsb  = (const float*)d_in[6];
    const float* Wtw  = (const float*)d_in[7];
    const float* Wtb  = (const float*)d_in[8];
    float* out = (float*)d_out;

    zero_kernel<<<2048, 256>>>();
    edge1_kernel<<<(N_EDGES + 7) / 8, 256>>>(h, esrc, edst);
    edge2_kernel<<<(N_EDGES + 7) / 8, 256>>>(h, esrc, edst);
    gemm_kernel<<<(N_NODES + 63) / 64, 256>>>(h, Ww, Wb, Wsw, Wsb, Wtw, Wtb, out);
}